// round 13
// baseline (speedup 1.0000x reference)
#include <cuda_runtime.h>
#include <cuda_bf16.h>
#include <cuda_fp8.h>
#include <math.h>
#include <stdint.h>

// Problem constants (fixed shapes)
#define BB 4
#define HH 64
#define WW 64
#define FF 256
#define CC 19
#define SS 256
#define TWOS (2*SS)            // 512
#define NN (BB*HH*WW)          // 16384 pixels
#define MM (CC*TWOS)           // 9728 memory vectors

// Scratch (static device globals; no allocation at runtime)
__device__ unsigned char g_A[NN * FF];   // e4m3 feats, [n][f] row-major (4 MB)
__device__ unsigned char g_Bm[MM * FF];  // e4m3 memory, [m][f] row-major (2.5 MB)
__device__ float g_sA[NN];               // 1/||quantized feat||
__device__ float g_sB[MM];               // 1/||quantized mem||
__device__ float g_total[NN];            // per-pixel sum of exp(cos/temp)
__device__ float g_blocksum[NN];         // per-pixel own-block sum of exp
__device__ float g_owncos[NN * TWOS];    // per-pixel own-class-block cos (33.5 MB)
__device__ float g_pixterm[NN];          // per-pixel positive-term sum

// ---------------------------------------------------------------------------
// exp(2*c) via MUFU: exp(2c) = 2^(2c*log2 e). ex2.approx rel err ~1e-6 here.
// ---------------------------------------------------------------------------
__device__ __forceinline__ float fexp2c(float c) {
    float y = c * 2.8853900817779268f;   // 2 * log2(e)
    float r;
    asm("ex2.approx.f32 %0, %1;" : "=f"(r) : "f"(y));
    return r;
}

__device__ __forceinline__ void cp16(uint32_t smem_dst, const void* gsrc) {
    asm volatile("cp.async.cg.shared.global [%0], [%1], 16;\n" :: "r"(smem_dst), "l"(gsrc));
}

__device__ __forceinline__ uint32_t smem_u32(const void* p) {
    uint32_t a;
    asm("{ .reg .u64 t; cvta.to.shared.u64 t, %1; cvt.u32.u64 %0, t; }" : "=r"(a) : "l"(p));
    return a;
}

__device__ __forceinline__ void ldm_x4(uint32_t* r, uint32_t addr) {
    asm volatile("ldmatrix.sync.aligned.m8n8.x4.shared.b16 {%0,%1,%2,%3}, [%4];"
        : "=r"(r[0]), "=r"(r[1]), "=r"(r[2]), "=r"(r[3]) : "r"(addr));
}

// m16n8k32 e4m3 x e4m3 -> f32
__device__ __forceinline__ void mma16832(float* d, const uint32_t* a, const uint32_t* b) {
    asm volatile(
        "mma.sync.aligned.m16n8k32.row.col.f32.e4m3.e4m3.f32 "
        "{%0,%1,%2,%3}, {%4,%5,%6,%7}, {%8,%9}, {%0,%1,%2,%3};\n"
        : "+f"(d[0]), "+f"(d[1]), "+f"(d[2]), "+f"(d[3])
        : "r"(a[0]), "r"(a[1]), "r"(a[2]), "r"(a[3]), "r"(b[0]), "r"(b[1]));
}

// ---------------------------------------------------------------------------
// K1a: normalize feats -> e4m3 [n][f] + post-quantization inverse norm.
// Also zero g_total/g_blocksum (rewritten each launch -> graph-deterministic).
// ---------------------------------------------------------------------------
__global__ void k_prep_feats(const float* __restrict__ pred) {
    int t = threadIdx.x;
    int w = t & 63;
    int h = blockIdx.y * 4 + (t >> 6);
    int b = blockIdx.x;
    int n = (b * HH + h) * WW + w;
    const float* base = pred + (size_t)b * FF * HH * WW + h * WW + w;

    float sumsq = 0.0f;
    #pragma unroll 8
    for (int f = 0; f < FF; f++) {
        float v = base[f * (HH * WW)];
        sumsq += v * v;
    }
    float inv = rsqrtf(sumsq);

    float qss = 0.0f;
    for (int f0 = 0; f0 < FF; f0 += 16) {
        union { unsigned char q[16]; uint4 u; } pk;
        #pragma unroll
        for (int j = 0; j < 16; j++) {
            float x = base[(f0 + j) * (HH * WW)] * inv;
            __nv_fp8_storage_t qs = __nv_cvt_float_to_fp8(x, __NV_SATFINITE, __NV_E4M3);
            pk.q[j] = (unsigned char)qs;
            float dq = (float)__nv_fp8_e4m3(x);   // dequantized value
            qss += dq * dq;
        }
        *(uint4*)&g_A[(size_t)n * FF + f0] = pk.u;
    }
    g_sA[n] = rsqrtf(qss);
    g_total[n] = 0.0f;
    g_blocksum[n] = 0.0f;
}

// ---------------------------------------------------------------------------
// K1b: normalize memory rows -> e4m3 [m][f] + inverse quantized norm.
// One block (128 thr) per row, 2 elems per thread.
// ---------------------------------------------------------------------------
__global__ void k_prep_mem(const float* __restrict__ mem) {
    __shared__ float red[4];
    __shared__ float red2[4];
    int m = blockIdx.x;
    int t = threadIdx.x;
    float2 v = *(const float2*)&mem[m * FF + 2 * t];
    float p = v.x * v.x + v.y * v.y;
    #pragma unroll
    for (int o = 16; o > 0; o >>= 1) p += __shfl_down_sync(0xffffffffu, p, o);
    if ((t & 31) == 0) red[t >> 5] = p;
    __syncthreads();
    float inv = rsqrtf(red[0] + red[1] + red[2] + red[3]);

    float x0 = v.x * inv, x1 = v.y * inv;
    __nv_fp8_e4m3 q0(x0), q1(x1);
    uchar2 o2;
    o2.x = (unsigned char)q0.__x;
    o2.y = (unsigned char)q1.__x;
    *(uchar2*)&g_Bm[(size_t)m * FF + 2 * t] = o2;

    float d0 = (float)q0, d1 = (float)q1;
    float q = d0 * d0 + d1 * d1;
    #pragma unroll
    for (int o = 16; o > 0; o >>= 1) q += __shfl_down_sync(0xffffffffu, q, o);
    if ((t & 31) == 0) red2[t >> 5] = q;
    __syncthreads();
    if (t == 0) g_sB[m] = rsqrtf(red2[0] + red2[1] + red2[2] + red2[3]);
}

// ---------------------------------------------------------------------------
// K2: e4m3 HMMA GEMM. CTA tile 128 pix x 128 mem, 128 threads (4 warps,
// 2x2), warp tile 64x64, mma.m16n8k32. BK=128 fp8, 2 stages fully
// prefetched. Epilogue rescales acc by sA*sB (exact cosine of quantized
// vectors), MUFU exp row sums + own-block sum + own-class cos scatter.
// ---------------------------------------------------------------------------
// Dynamic smem (bytes): labels[128]@0, rowsum@512, blksum@1024, sA@1536,
// sB@2048, A stages @4096 (2 x 16KB), B stages @36864 (2 x 16KB). Tot 69632.
#define SM_LAB   0
#define SM_PART  512
#define SM_BPART 1024
#define SM_SA    1536
#define SM_SB    2048
#define SM_A     4096
#define SM_B     (4096 + 2*16384)
#define SM_TOTAL (4096 + 4*16384)

__global__ __launch_bounds__(128, 2) void k_gemm(const int* __restrict__ labels) {
    extern __shared__ __align__(1024) char dsm[];
    uint32_t sb = smem_u32(dsm);

    int tid = threadIdx.x;
    int m0 = blockIdx.x * 128;
    int n0 = blockIdx.y * 128;
    int wid = tid >> 5, lane = tid & 31;
    int wmw = wid & 1;          // pixel-dir warp (2): rows [wmw*64, +64)
    int wnw = wid >> 1;         // mem-dir warp (2): cols [wnw*64, +64)
    int g = lane >> 2, t4 = lane & 3;
    int l15 = lane & 15, l16 = lane >> 4;

    float* s_rowsum = (float*)(dsm + SM_PART);
    float* s_blksum = (float*)(dsm + SM_BPART);
    float* s_sA     = (float*)(dsm + SM_SA);
    float* s_sB     = (float*)(dsm + SM_SB);
    int*   s_lab    = (int*)(dsm + SM_LAB);

    s_rowsum[tid] = 0.0f;
    s_blksum[tid] = 0.0f;
    s_lab[tid] = labels[n0 + tid];
    s_sA[tid] = g_sA[n0 + tid];
    s_sB[tid] = g_sB[m0 + tid];

    float acc[4][8][4];
    #pragma unroll
    for (int mi = 0; mi < 4; mi++)
        #pragma unroll
        for (int ni = 0; ni < 8; ni++)
            #pragma unroll
            for (int q = 0; q < 4; q++) acc[mi][ni][q] = 0.0f;

    // Fill one BK=128(fp8) stage: A 1024 + B 1024 16B-chunks over 128 threads.
#define ISSUE(IT, BUF) do {                                                     \
        int k0_ = (IT) * 128;                                                   \
        _Pragma("unroll")                                                       \
        for (int r_ = 0; r_ < 8; r_++) {                                        \
            int id = tid + r_ * 128;          /* 0..1023 */                     \
            int row = id >> 3, c = id & 7;                                      \
            int sw = (c ^ (row & 7)) << 4;                                      \
            cp16(sb + SM_A + (BUF) * 16384 + row * 128 + sw,                    \
                 &g_A[(size_t)(n0 + row) * FF + k0_ + c * 16]);                 \
            cp16(sb + SM_B + (BUF) * 16384 + row * 128 + sw,                    \
                 &g_Bm[(size_t)(m0 + row) * FF + k0_ + c * 16]);                \
        } } while (0)

    ISSUE(0, 0);
    asm volatile("cp.async.commit_group;\n");
    ISSUE(1, 1);
    asm volatile("cp.async.commit_group;\n");

    #pragma unroll
    for (int it = 0; it < 2; it++) {
        if (it == 0) asm volatile("cp.async.wait_group 1;\n" ::: "memory");
        else         asm volatile("cp.async.wait_group 0;\n" ::: "memory");
        __syncthreads();

        uint32_t Ab = sb + SM_A + it * 16384;
        uint32_t Bb = sb + SM_B + it * 16384;
        #pragma unroll
        for (int ks = 0; ks < 4; ks++) {
            int kc = ks * 2 + l16;           // 16B chunk index (2 per k32)
            uint32_t a[4][4], b[4][4];
            #pragma unroll
            for (int mi = 0; mi < 4; mi++) {
                int row = wmw * 64 + mi * 16 + l15;
                ldm_x4(a[mi], Ab + row * 128 + ((kc ^ (row & 7)) << 4));
            }
            #pragma unroll
            for (int nj = 0; nj < 4; nj++) {
                int row = wnw * 64 + nj * 16 + l15;
                ldm_x4(b[nj], Bb + row * 128 + ((kc ^ (row & 7)) << 4));
            }
            #pragma unroll
            for (int mi = 0; mi < 4; mi++)
                #pragma unroll
                for (int nj = 0; nj < 4; nj++) {
                    uint32_t b0[2] = { b[nj][0], b[nj][2] };
                    uint32_t b1[2] = { b[nj][1], b[nj][3] };
                    mma16832(acc[mi][2 * nj],     a[mi], b0);
                    mma16832(acc[mi][2 * nj + 1], a[mi], b1);
                }
        }
        if (it == 0) __syncthreads();
    }
#undef ISSUE
    __syncthreads();

    // Epilogue: rescale by sA*sB, MUFU exp + row sums + own-block sums +
    // own-class cos scatter. 128-aligned m-window lies in one class block.
    int cls = m0 >> 9;
    int mbase = (m0 & 511) + wnw * 64;

    #pragma unroll
    for (int mi = 0; mi < 4; mi++) {
        int p0 = wmw * 64 + mi * 16 + g;
        int p1 = p0 + 8;
        bool own0 = (s_lab[p0] == cls);
        bool own1 = (s_lab[p1] == cls);
        float sa0 = s_sA[p0], sa1 = s_sA[p1];
        float s0 = 0.0f, s1 = 0.0f;
        #pragma unroll
        for (int ni = 0; ni < 8; ni++) {
            int cl = wnw * 64 + ni * 8 + t4 * 2;   // tile-local col
            float sb0 = s_sB[cl], sb1 = s_sB[cl + 1];
            float d0 = acc[mi][ni][0] * sa0 * sb0;
            float d1 = acc[mi][ni][1] * sa0 * sb1;
            float d2 = acc[mi][ni][2] * sa1 * sb0;
            float d3 = acc[mi][ni][3] * sa1 * sb1;
            s0 += fexp2c(d0) + fexp2c(d1);
            s1 += fexp2c(d2) + fexp2c(d3);
            int mo = mbase + ni * 8 + t4 * 2;
            if (own0) {
                float2 v; v.x = d0; v.y = d1;
                *(float2*)&g_owncos[(size_t)(n0 + p0) * TWOS + mo] = v;
            }
            if (own1) {
                float2 v; v.x = d2; v.y = d3;
                *(float2*)&g_owncos[(size_t)(n0 + p1) * TWOS + mo] = v;
            }
        }
        s0 += __shfl_xor_sync(0xffffffffu, s0, 1);
        s0 += __shfl_xor_sync(0xffffffffu, s0, 2);
        s1 += __shfl_xor_sync(0xffffffffu, s1, 1);
        s1 += __shfl_xor_sync(0xffffffffu, s1, 2);
        if (t4 == 0) {
            atomicAdd(&s_rowsum[p0], s0);
            atomicAdd(&s_rowsum[p1], s1);
            if (own0) atomicAdd(&s_blksum[p0], s0);
            if (own1) atomicAdd(&s_blksum[p1], s1);
        }
    }
    __syncthreads();
    atomicAdd(&g_total[n0 + tid], s_rowsum[tid]);
    {
        float bsv = s_blksum[tid];
        if (bsv != 0.0f) atomicAdd(&g_blocksum[n0 + tid], bsv);
    }
}

// ---------------------------------------------------------------------------
// K3: one warp per pixel. down = total - blocksum; only the wm-selected
// half (256 values): sum -log(pos/(pos+down+eps)+eps).
// ---------------------------------------------------------------------------
__global__ void k_terms(const unsigned char* __restrict__ mask,
                        const int* __restrict__ wm) {
    int gw   = (blockIdx.x * blockDim.x + threadIdx.x) >> 5;
    int lane = threadIdx.x & 31;
    if (gw >= NN) return;
    int n = gw;

    int wv = wm[n];
    int hb = (wv == 1) ? 0 : SS;   // wm==1 -> net0 -> first half
    float down = g_total[n] - g_blocksum[n];

    float ts = 0.0f;
    #pragma unroll
    for (int k = 0; k < 8; k++) {
        float c = g_owncos[(size_t)n * TWOS + hb + lane + 32 * k];
        float pos = fexp2c(c);
        float r = pos / (pos + down + 1e-12f);
        ts += -logf(r + 1e-12f);
    }
    #pragma unroll
    for (int o = 16; o > 0; o >>= 1) ts += __shfl_xor_sync(0xffffffffu, ts, o);

    if (lane == 0) g_pixterm[n] = mask[n] ? ts : 0.0f;
}

// ---------------------------------------------------------------------------
// K4: per-class reduction -> final scalar.
// ---------------------------------------------------------------------------
__global__ void k_final(const int* __restrict__ labels,
                        const unsigned char* __restrict__ mask,
                        float* __restrict__ out) {
    __shared__ float contrib[CC];
    __shared__ int   cnt[CC];
    int t = threadIdx.x;
    if (t < CC) { contrib[t] = 0.0f; cnt[t] = 0; }
    __syncthreads();
    for (int n = t; n < NN; n += blockDim.x) {
        if (mask[n]) {
            int c = labels[n];
            atomicAdd(&contrib[c], g_pixterm[n]);
            atomicAdd(&cnt[c], 1);
        }
    }
    __syncthreads();
    if (t == 0) {
        float loss = 0.0f, ccount = 0.0f;
        for (int i = 0; i < CC; i++) {
            if (cnt[i] > 0) {
                loss += contrib[i] / ((float)cnt[i] * (float)SS);
                ccount += 1.0f;
            }
        }
        out[0] = loss / fmaxf(ccount, 1.0f);
    }
}

// ---------------------------------------------------------------------------
extern "C" void kernel_launch(void* const* d_in, const int* in_sizes, int n_in,
                              void* d_out, int out_size) {
    const float*         mem    = (const float*)d_in[0];         // (19,512,256)
    const float*         pred   = (const float*)d_in[1];         // (4,256,64,64)
    const int*           labels = (const int*)d_in[2];           // (4,64,64)
    const unsigned char* mask   = (const unsigned char*)d_in[3]; // bool (1B)
    const int*           wm     = (const int*)d_in[4];           // (4,64,64)
    float*               out    = (float*)d_out;

    (void)in_sizes; (void)n_in; (void)out_size;

    cudaFuncSetAttribute(k_gemm, cudaFuncAttributeMaxDynamicSharedMemorySize, SM_TOTAL);

    k_prep_feats<<<dim3(BB, HH / 4), 256>>>(pred);
    k_prep_mem<<<MM, 128>>>(mem);
    k_gemm<<<dim3(MM / 128, NN / 128), 128, SM_TOTAL>>>(labels);
    k_terms<<<NN / 8, 256>>>(mask, wm);
    k_final<<<1, 256>>>(labels, mask, out);
}

// round 14
// speedup vs baseline: 1.1573x; 1.1573x over previous
#include <cuda_runtime.h>
#include <cuda_bf16.h>
#include <math.h>
#include <stdint.h>

// Problem constants (fixed shapes)
#define BB 4
#define HH 64
#define WW 64
#define FF 256
#define CC 19
#define SS 256
#define TWOS (2*SS)            // 512
#define NN (BB*HH*WW)          // 16384 pixels
#define MM (CC*TWOS)           // 9728 memory vectors

// Scratch (static device globals; no allocation at runtime)
__device__ __nv_bfloat16 g_A[NN * FF];   // normalized feats, [n][f] row-major (8 MB)
__device__ __nv_bfloat16 g_Bm[MM * FF];  // normalized memory, [m][f] row-major (5 MB)
__device__ float g_total[NN];            // per-pixel sum of exp(cos/temp)
__device__ float g_blocksum[NN];         // per-pixel own-block sum of exp
__device__ float g_owncos[NN * SS];      // per-pixel SELECTED-half cos (16.8 MB)
__device__ float g_pixterm[NN];          // per-pixel positive-term sum

// ---------------------------------------------------------------------------
// exp(2*c) via MUFU: exp(2c) = 2^(2c*log2 e). ex2.approx rel err ~1e-6 here.
// ---------------------------------------------------------------------------
__device__ __forceinline__ float fexp2c(float c) {
    float y = c * 2.8853900817779268f;   // 2 * log2(e)
    float r;
    asm("ex2.approx.f32 %0, %1;" : "=f"(r) : "f"(y));
    return r;
}

__device__ __forceinline__ void cp16(uint32_t smem_dst, const void* gsrc) {
    asm volatile("cp.async.cg.shared.global [%0], [%1], 16;\n" :: "r"(smem_dst), "l"(gsrc));
}

__device__ __forceinline__ uint32_t smem_u32(const void* p) {
    uint32_t a;
    asm("{ .reg .u64 t; cvta.to.shared.u64 t, %1; cvt.u32.u64 %0, t; }" : "=r"(a) : "l"(p));
    return a;
}

__device__ __forceinline__ void ldm_x4(uint32_t* r, uint32_t addr) {
    asm volatile("ldmatrix.sync.aligned.m8n8.x4.shared.b16 {%0,%1,%2,%3}, [%4];"
        : "=r"(r[0]), "=r"(r[1]), "=r"(r[2]), "=r"(r[3]) : "r"(addr));
}

__device__ __forceinline__ void mma16816(float* d, const uint32_t* a, const uint32_t* b) {
    asm volatile(
        "mma.sync.aligned.m16n8k16.row.col.f32.bf16.bf16.f32 "
        "{%0,%1,%2,%3}, {%4,%5,%6,%7}, {%8,%9}, {%0,%1,%2,%3};\n"
        : "+f"(d[0]), "+f"(d[1]), "+f"(d[2]), "+f"(d[3])
        : "r"(a[0]), "r"(a[1]), "r"(a[2]), "r"(a[3]), "r"(b[0]), "r"(b[1]));
}

// ---------------------------------------------------------------------------
// K1: fused prep. Blocks [0,64): normalize feats (B,F,H,W) -> bf16 [n][f],
// zero totals. Blocks [64, 64+4864): normalize 2 memory rows each -> bf16.
// ---------------------------------------------------------------------------
__global__ void k_prep(const float* __restrict__ pred,
                       const float* __restrict__ mem) {
    int blk = blockIdx.x;
    int t = threadIdx.x;

    if (blk < 64) {
        // ---- feats path: 256 threads = 4 rows of 64 pixels ----
        int w = t & 63;
        int h = (blk & 15) * 4 + (t >> 6);
        int b = blk >> 4;
        int n = (b * HH + h) * WW + w;
        const float* base = pred + (size_t)b * FF * HH * WW + h * WW + w;

        float sumsq = 0.0f;
        #pragma unroll 8
        for (int f = 0; f < FF; f++) {
            float v = base[f * (HH * WW)];
            sumsq += v * v;
        }
        float inv = rsqrtf(sumsq);

        for (int f0 = 0; f0 < FF; f0 += 8) {
            __nv_bfloat16 h8[8];
            #pragma unroll
            for (int j = 0; j < 8; j++)
                h8[j] = __float2bfloat16(base[(f0 + j) * (HH * WW)] * inv);
            *(uint4*)&g_A[(size_t)n * FF + f0] = *(const uint4*)h8;
        }
        g_total[n] = 0.0f;
        g_blocksum[n] = 0.0f;
    } else {
        // ---- memory path: 256 threads = 2 rows, 128 threads each ----
        __shared__ float red[8];
        int half = t >> 7;             // 0 or 1
        int tl = t & 127;
        int m = (blk - 64) * 2 + half;
        int wid = t >> 5;              // 0..7; warps 0-3 = row0, 4-7 = row1

        float2 v = *(const float2*)&mem[(size_t)m * FF + 2 * tl];
        float p = v.x * v.x + v.y * v.y;
        #pragma unroll
        for (int o = 16; o > 0; o >>= 1) p += __shfl_down_sync(0xffffffffu, p, o);
        if ((t & 31) == 0) red[wid] = p;
        __syncthreads();
        float inv = rsqrtf(red[half * 4 + 0] + red[half * 4 + 1]
                         + red[half * 4 + 2] + red[half * 4 + 3]);
        __nv_bfloat162 o2;
        o2.x = __float2bfloat16(v.x * inv);
        o2.y = __float2bfloat16(v.y * inv);
        *(__nv_bfloat162*)&g_Bm[(size_t)m * FF + 2 * tl] = o2;
    }
}

// ---------------------------------------------------------------------------
// K2: bf16 HMMA GEMM. CTA tile 128 pix x 128 mem, 128 threads (4 warps,
// 2x2 grid), warp tile 64x64. BK=64, 3-stage cp.async pipeline, ldmatrix
// + XOR swizzle, register double-buffered fragments. 2 CTAs/SM.
// Epilogue: MUFU exp row sums + own-block sum + wm-selected cos scatter.
// ---------------------------------------------------------------------------
// Dynamic smem (bytes): labels[128]@0, rowsum@512, blksum@1024, hb[128]@1536,
// A stages @2048 (3 x 16KB), B stages @51200 (3 x 16KB). Total 100352.
#define SM_LAB   0
#define SM_PART  512
#define SM_BPART 1024
#define SM_HB    1536
#define SM_A     2048
#define SM_B     (2048 + 3*16384)
#define SM_TOTAL (2048 + 6*16384)

__global__ __launch_bounds__(128, 2) void k_gemm(const int* __restrict__ labels,
                                                 const int* __restrict__ wm) {
    extern __shared__ __align__(1024) char dsm[];
    uint32_t sb = smem_u32(dsm);

    int tid = threadIdx.x;
    int m0 = blockIdx.x * 128;
    int n0 = blockIdx.y * 128;
    int wid = tid >> 5, lane = tid & 31;
    int wmw = wid & 1;          // pixel-dir warp (2): rows [wmw*64, +64)
    int wnw = wid >> 1;         // mem-dir warp (2): cols [wnw*64, +64)
    int g = lane >> 2, t4 = lane & 3;
    int l15 = lane & 15, l16 = lane >> 4;

    float* s_rowsum = (float*)(dsm + SM_PART);
    float* s_blksum = (float*)(dsm + SM_BPART);
    int*   s_lab    = (int*)(dsm + SM_LAB);
    int*   s_hb     = (int*)(dsm + SM_HB);

    s_rowsum[tid] = 0.0f;
    s_blksum[tid] = 0.0f;
    s_lab[tid] = labels[n0 + tid];
    s_hb[tid] = (wm[n0 + tid] == 1) ? 0 : 1;   // selected half index (0=first)

    float acc[4][8][4];
    #pragma unroll
    for (int mi = 0; mi < 4; mi++)
        #pragma unroll
        for (int ni = 0; ni < 8; ni++)
            #pragma unroll
            for (int q = 0; q < 4; q++) acc[mi][ni][q] = 0.0f;

    // Fill one BK=64 stage: A 1024 + B 1024 16B-chunks over 128 threads.
#define ISSUE(IT, BUF) do {                                                     \
        int k0_ = (IT) * 64;                                                    \
        _Pragma("unroll")                                                       \
        for (int r_ = 0; r_ < 8; r_++) {                                        \
            int id = tid + r_ * 128;          /* 0..1023 */                     \
            int row = id >> 3, c = id & 7;                                      \
            int sw = (c ^ (row & 7)) << 4;                                      \
            cp16(sb + SM_A + (BUF) * 16384 + row * 128 + sw,                    \
                 &g_A[(size_t)(n0 + row) * FF + k0_ + c * 8]);                  \
            cp16(sb + SM_B + (BUF) * 16384 + row * 128 + sw,                    \
                 &g_Bm[(size_t)(m0 + row) * FF + k0_ + c * 8]);                 \
        } } while (0)

    // Load the 8 fragments for k-chunk kc from stage buffers.
#define LOADFRAG(FA, FB, Ab, Bb, KC) do {                                       \
        _Pragma("unroll")                                                       \
        for (int mi_ = 0; mi_ < 4; mi_++) {                                     \
            int row = wmw * 64 + mi_ * 16 + l15;                                \
            ldm_x4(FA[mi_], (Ab) + row * 128 + (((KC) ^ (row & 7)) << 4));      \
        }                                                                       \
        _Pragma("unroll")                                                       \
        for (int nj_ = 0; nj_ < 4; nj_++) {                                     \
            int row = wnw * 64 + nj_ * 16 + l15;                                \
            ldm_x4(FB[nj_], (Bb) + row * 128 + (((KC) ^ (row & 7)) << 4));      \
        } } while (0)

#define DOMMA(FA, FB) do {                                                      \
        _Pragma("unroll")                                                       \
        for (int mi_ = 0; mi_ < 4; mi_++)                                       \
            _Pragma("unroll")                                                   \
            for (int nj_ = 0; nj_ < 4; nj_++) {                                 \
                uint32_t b0_[2] = { FB[nj_][0], FB[nj_][2] };                   \
                uint32_t b1_[2] = { FB[nj_][1], FB[nj_][3] };                   \
                mma16816(acc[mi_][2 * nj_],     FA[mi_], b0_);                  \
                mma16816(acc[mi_][2 * nj_ + 1], FA[mi_], b1_);                  \
            } } while (0)

    ISSUE(0, 0);
    asm volatile("cp.async.commit_group;\n");
    ISSUE(1, 1);
    asm volatile("cp.async.commit_group;\n");

    uint32_t fa[2][4][4], fb[2][4][4];

    #pragma unroll
    for (int it = 0; it < 4; it++) {
        if (it < 3) asm volatile("cp.async.wait_group 1;\n" ::: "memory");
        else        asm volatile("cp.async.wait_group 0;\n" ::: "memory");
        __syncthreads();
        if (it < 2) {
            ISSUE(it + 2, (it + 2) % 3);
            asm volatile("cp.async.commit_group;\n");
        }

        int buf = it % 3;
        uint32_t Ab = sb + SM_A + buf * 16384;
        uint32_t Bb = sb + SM_B + buf * 16384;

        // Register-double-buffered fragment pipeline over 4 k-chunks.
        LOADFRAG(fa[0], fb[0], Ab, Bb, (0 * 2 + l16));
        #pragma unroll
        for (int ks = 0; ks < 4; ks++) {
            int cur = ks & 1;
            if (ks < 3)
                LOADFRAG(fa[cur ^ 1], fb[cur ^ 1], Ab, Bb, ((ks + 1) * 2 + l16));
            DOMMA(fa[cur], fb[cur]);
        }
    }
#undef ISSUE
#undef LOADFRAG
#undef DOMMA
    __syncthreads();

    // Epilogue: MUFU exp + row sums + own-block sums + wm-selected cos
    // scatter. 128-aligned m-window lies in one 512-wide class block.
    int cls = m0 >> 9;
    int mbase = (m0 & 511) + wnw * 64;   // 64-aligned offset in class block
    int msel = mbase >> 8;               // which half this warp's cols fall in
    int moff = mbase & 255;              // offset within that half

    #pragma unroll
    for (int mi = 0; mi < 4; mi++) {
        int p0 = wmw * 64 + mi * 16 + g;
        int p1 = p0 + 8;
        bool own0 = (s_lab[p0] == cls);
        bool own1 = (s_lab[p1] == cls);
        bool sel0 = own0 && (s_hb[p0] == msel);
        bool sel1 = own1 && (s_hb[p1] == msel);
        float s0 = 0.0f, s1 = 0.0f;
        #pragma unroll
        for (int ni = 0; ni < 8; ni++) {
            float d0 = acc[mi][ni][0], d1 = acc[mi][ni][1];
            float d2 = acc[mi][ni][2], d3 = acc[mi][ni][3];
            s0 += fexp2c(d0) + fexp2c(d1);
            s1 += fexp2c(d2) + fexp2c(d3);
            int mo = moff + ni * 8 + t4 * 2;
            if (sel0) {
                float2 v; v.x = d0; v.y = d1;
                *(float2*)&g_owncos[(size_t)(n0 + p0) * SS + mo] = v;
            }
            if (sel1) {
                float2 v; v.x = d2; v.y = d3;
                *(float2*)&g_owncos[(size_t)(n0 + p1) * SS + mo] = v;
            }
        }
        s0 += __shfl_xor_sync(0xffffffffu, s0, 1);
        s0 += __shfl_xor_sync(0xffffffffu, s0, 2);
        s1 += __shfl_xor_sync(0xffffffffu, s1, 1);
        s1 += __shfl_xor_sync(0xffffffffu, s1, 2);
        if (t4 == 0) {
            atomicAdd(&s_rowsum[p0], s0);
            atomicAdd(&s_rowsum[p1], s1);
            if (own0) atomicAdd(&s_blksum[p0], s0);
            if (own1) atomicAdd(&s_blksum[p1], s1);
        }
    }
    __syncthreads();
    atomicAdd(&g_total[n0 + tid], s_rowsum[tid]);
    {
        float bsv = s_blksum[tid];
        if (bsv != 0.0f) atomicAdd(&g_blocksum[n0 + tid], bsv);
    }
}

// ---------------------------------------------------------------------------
// K3: one warp per pixel. down = total - blocksum; the stored values are
// already the wm-selected half: sum -log(pos/(pos+down+eps)+eps).
// ---------------------------------------------------------------------------
__global__ void k_terms(const unsigned char* __restrict__ mask) {
    int gw   = (blockIdx.x * blockDim.x + threadIdx.x) >> 5;
    int lane = threadIdx.x & 31;
    if (gw >= NN) return;
    int n = gw;

    float down = g_total[n] - g_blocksum[n];

    float ts = 0.0f;
    #pragma unroll
    for (int k = 0; k < 8; k++) {
        float c = g_owncos[(size_t)n * SS + lane + 32 * k];
        float pos = fexp2c(c);
        float r = pos / (pos + down + 1e-12f);
        ts += -logf(r + 1e-12f);
    }
    #pragma unroll
    for (int o = 16; o > 0; o >>= 1) ts += __shfl_xor_sync(0xffffffffu, ts, o);

    if (lane == 0) g_pixterm[n] = mask[n] ? ts : 0.0f;
}

// ---------------------------------------------------------------------------
// K4: per-class reduction -> final scalar.
// ---------------------------------------------------------------------------
__global__ void k_final(const int* __restrict__ labels,
                        const unsigned char* __restrict__ mask,
                        float* __restrict__ out) {
    __shared__ float contrib[CC];
    __shared__ int   cnt[CC];
    int t = threadIdx.x;
    if (t < CC) { contrib[t] = 0.0f; cnt[t] = 0; }
    __syncthreads();
    for (int n = t; n < NN; n += blockDim.x) {
        if (mask[n]) {
            int c = labels[n];
            atomicAdd(&contrib[c], g_pixterm[n]);
            atomicAdd(&cnt[c], 1);
        }
    }
    __syncthreads();
    if (t == 0) {
        float loss = 0.0f, ccount = 0.0f;
        for (int i = 0; i < CC; i++) {
            if (cnt[i] > 0) {
                loss += contrib[i] / ((float)cnt[i] * (float)SS);
                ccount += 1.0f;
            }
        }
        out[0] = loss / fmaxf(ccount, 1.0f);
    }
}

// ---------------------------------------------------------------------------
extern "C" void kernel_launch(void* const* d_in, const int* in_sizes, int n_in,
                              void* d_out, int out_size) {
    const float*         mem    = (const float*)d_in[0];         // (19,512,256)
    const float*         pred   = (const float*)d_in[1];         // (4,256,64,64)
    const int*           labels = (const int*)d_in[2];           // (4,64,64)
    const unsigned char* mask   = (const unsigned char*)d_in[3]; // bool (1B)
    const int*           wm     = (const int*)d_in[4];           // (4,64,64)
    float*               out    = (float*)d_out;

    (void)in_sizes; (void)n_in; (void)out_size;

    cudaFuncSetAttribute(k_gemm, cudaFuncAttributeMaxDynamicSharedMemorySize, SM_TOTAL);

    k_prep<<<64 + MM / 2, 256>>>(pred, mem);
    k_gemm<<<dim3(MM / 128, NN / 128), 128, SM_TOTAL>>>(labels, wm);
    k_terms<<<NN / 8, 256>>>(mask);
    k_final<<<1, 256>>>(labels, mask, out);
}

// round 16
// speedup vs baseline: 1.3241x; 1.1442x over previous
#include <cuda_runtime.h>
#include <cuda_bf16.h>
#include <math.h>
#include <stdint.h>

// Problem constants (fixed shapes)
#define BB 4
#define HH 64
#define WW 64
#define FF 256
#define CC 19
#define SS 256
#define TWOS (2*SS)            // 512
#define NN (BB*HH*WW)          // 16384 pixels
#define MM (CC*TWOS)           // 9728 memory vectors

// Scratch (static device globals; no allocation at runtime)
__device__ __nv_bfloat16 g_A[NN * FF];   // normalized feats, [n][f] row-major (8 MB)
__device__ __nv_bfloat16 g_Bm[MM * FF];  // normalized memory, [m][f] row-major (5 MB)
__device__ float g_total[NN];            // per-pixel sum of exp(cos/temp)
__device__ float g_blocksum[NN];         // per-pixel own-block sum of exp
__device__ float g_owncos[NN * SS];      // per-pixel SELECTED-half cos (16.8 MB)
__device__ float g_contrib[CC];          // per-class contribution accumulator
__device__ int   g_cnt[CC];              // per-class masked-pixel count

// ---------------------------------------------------------------------------
// exp(2*c) via MUFU: exp(2c) = 2^(2c*log2 e). ex2.approx rel err ~1e-6 here.
// ---------------------------------------------------------------------------
__device__ __forceinline__ float fexp2c(float c) {
    float y = c * 2.8853900817779268f;   // 2 * log2(e)
    float r;
    asm("ex2.approx.f32 %0, %1;" : "=f"(r) : "f"(y));
    return r;
}

__device__ __forceinline__ void cp16(uint32_t smem_dst, const void* gsrc) {
    asm volatile("cp.async.cg.shared.global [%0], [%1], 16;\n" :: "r"(smem_dst), "l"(gsrc));
}

__device__ __forceinline__ uint32_t smem_u32(const void* p) {
    uint32_t a;
    asm("{ .reg .u64 t; cvta.to.shared.u64 t, %1; cvt.u32.u64 %0, t; }" : "=r"(a) : "l"(p));
    return a;
}

__device__ __forceinline__ void ldm_x4(uint32_t* r, uint32_t addr) {
    asm volatile("ldmatrix.sync.aligned.m8n8.x4.shared.b16 {%0,%1,%2,%3}, [%4];"
        : "=r"(r[0]), "=r"(r[1]), "=r"(r[2]), "=r"(r[3]) : "r"(addr));
}

__device__ __forceinline__ void mma16816(float* d, const uint32_t* a, const uint32_t* b) {
    asm volatile(
        "mma.sync.aligned.m16n8k16.row.col.f32.bf16.bf16.f32 "
        "{%0,%1,%2,%3}, {%4,%5,%6,%7}, {%8,%9}, {%0,%1,%2,%3};\n"
        : "+f"(d[0]), "+f"(d[1]), "+f"(d[2]), "+f"(d[3])
        : "r"(a[0]), "r"(a[1]), "r"(a[2]), "r"(a[3]), "r"(b[0]), "r"(b[1]));
}

// ---------------------------------------------------------------------------
// K1: fused prep. Blocks [0,64): normalize feats (B,F,H,W) -> bf16 [n][f],
// zero totals. Blocks [64, 64+4864): normalize 2 memory rows each -> bf16.
// Block 64 thread 0..CC also zeroes the per-class accumulators.
// ---------------------------------------------------------------------------
__global__ void k_prep(const float* __restrict__ pred,
                       const float* __restrict__ mem) {
    int blk = blockIdx.x;
    int t = threadIdx.x;

    if (blk < 64) {
        // ---- feats path: 256 threads = 4 rows of 64 pixels ----
        int w = t & 63;
        int h = (blk & 15) * 4 + (t >> 6);
        int b = blk >> 4;
        int n = (b * HH + h) * WW + w;
        const float* base = pred + (size_t)b * FF * HH * WW + h * WW + w;

        float sumsq = 0.0f;
        #pragma unroll 8
        for (int f = 0; f < FF; f++) {
            float v = base[f * (HH * WW)];
            sumsq += v * v;
        }
        float inv = rsqrtf(sumsq);

        for (int f0 = 0; f0 < FF; f0 += 8) {
            __nv_bfloat16 h8[8];
            #pragma unroll
            for (int j = 0; j < 8; j++)
                h8[j] = __float2bfloat16(base[(f0 + j) * (HH * WW)] * inv);
            *(uint4*)&g_A[(size_t)n * FF + f0] = *(const uint4*)h8;
        }
        g_total[n] = 0.0f;
        g_blocksum[n] = 0.0f;
    } else {
        // ---- memory path: 256 threads = 2 rows, 128 threads each ----
        __shared__ float red[8];
        int half = t >> 7;             // 0 or 1
        int tl = t & 127;
        int m = (blk - 64) * 2 + half;
        int wid = t >> 5;              // 0..7; warps 0-3 = row0, 4-7 = row1

        if (blk == 64 && t < CC) { g_contrib[t] = 0.0f; g_cnt[t] = 0; }

        float2 v = *(const float2*)&mem[(size_t)m * FF + 2 * tl];
        float p = v.x * v.x + v.y * v.y;
        #pragma unroll
        for (int o = 16; o > 0; o >>= 1) p += __shfl_down_sync(0xffffffffu, p, o);
        if ((t & 31) == 0) red[wid] = p;
        __syncthreads();
        float inv = rsqrtf(red[half * 4 + 0] + red[half * 4 + 1]
                         + red[half * 4 + 2] + red[half * 4 + 3]);
        __nv_bfloat162 o2;
        o2.x = __float2bfloat16(v.x * inv);
        o2.y = __float2bfloat16(v.y * inv);
        *(__nv_bfloat162*)&g_Bm[(size_t)m * FF + 2 * tl] = o2;
    }
}

// ---------------------------------------------------------------------------
// K2: bf16 HMMA GEMM. CTA tile 128 pix x 128 mem, 128 threads (4 warps,
// 2x2 grid), warp tile 64x64. BK=64, 3-stage cp.async pipeline, ldmatrix
// + XOR swizzle, register double-buffered fragments. 2 CTAs/SM.
// Epilogue: MUFU exp row sums + own-block sum + wm-selected cos scatter.
// ---------------------------------------------------------------------------
// Dynamic smem (bytes): labels[128]@0, rowsum@512, blksum@1024, hb[128]@1536,
// A stages @2048 (3 x 16KB), B stages @51200 (3 x 16KB). Total 100352.
#define SM_LAB   0
#define SM_PART  512
#define SM_BPART 1024
#define SM_HB    1536
#define SM_A     2048
#define SM_B     (2048 + 3*16384)
#define SM_TOTAL (2048 + 6*16384)

__global__ __launch_bounds__(128, 2) void k_gemm(const int* __restrict__ labels,
                                                 const int* __restrict__ wm) {
    extern __shared__ __align__(1024) char dsm[];
    uint32_t sb = smem_u32(dsm);

    int tid = threadIdx.x;
    int m0 = blockIdx.x * 128;
    int n0 = blockIdx.y * 128;
    int wid = tid >> 5, lane = tid & 31;
    int wmw = wid & 1;          // pixel-dir warp (2): rows [wmw*64, +64)
    int wnw = wid >> 1;         // mem-dir warp (2): cols [wnw*64, +64)
    int g = lane >> 2, t4 = lane & 3;
    int l15 = lane & 15, l16 = lane >> 4;

    float* s_rowsum = (float*)(dsm + SM_PART);
    float* s_blksum = (float*)(dsm + SM_BPART);
    int*   s_lab    = (int*)(dsm + SM_LAB);
    int*   s_hb     = (int*)(dsm + SM_HB);

    s_rowsum[tid] = 0.0f;
    s_blksum[tid] = 0.0f;
    s_lab[tid] = labels[n0 + tid];
    s_hb[tid] = (wm[n0 + tid] == 1) ? 0 : 1;   // selected half index (0=first)

    float acc[4][8][4];
    #pragma unroll
    for (int mi = 0; mi < 4; mi++)
        #pragma unroll
        for (int ni = 0; ni < 8; ni++)
            #pragma unroll
            for (int q = 0; q < 4; q++) acc[mi][ni][q] = 0.0f;

    // Fill one BK=64 stage: A 1024 + B 1024 16B-chunks over 128 threads.
#define ISSUE(IT, BUF) do {                                                     \
        int k0_ = (IT) * 64;                                                    \
        _Pragma("unroll")                                                       \
        for (int r_ = 0; r_ < 8; r_++) {                                        \
            int id = tid + r_ * 128;          /* 0..1023 */                     \
            int row = id >> 3, c = id & 7;                                      \
            int sw = (c ^ (row & 7)) << 4;                                      \
            cp16(sb + SM_A + (BUF) * 16384 + row * 128 + sw,                    \
                 &g_A[(size_t)(n0 + row) * FF + k0_ + c * 8]);                  \
            cp16(sb + SM_B + (BUF) * 16384 + row * 128 + sw,                    \
                 &g_Bm[(size_t)(m0 + row) * FF + k0_ + c * 8]);                 \
        } } while (0)

    // Load the 8 fragments for k-chunk kc from stage buffers.
#define LOADFRAG(FA, FB, Ab, Bb, KC) do {                                       \
        _Pragma("unroll")                                                       \
        for (int mi_ = 0; mi_ < 4; mi_++) {                                     \
            int row = wmw * 64 + mi_ * 16 + l15;                                \
            ldm_x4(FA[mi_], (Ab) + row * 128 + (((KC) ^ (row & 7)) << 4));      \
        }                                                                       \
        _Pragma("unroll")                                                       \
        for (int nj_ = 0; nj_ < 4; nj_++) {                                     \
            int row = wnw * 64 + nj_ * 16 + l15;                                \
            ldm_x4(FB[nj_], (Bb) + row * 128 + (((KC) ^ (row & 7)) << 4));      \
        } } while (0)

#define DOMMA(FA, FB) do {                                                      \
        _Pragma("unroll")                                                       \
        for (int mi_ = 0; mi_ < 4; mi_++)                                       \
            _Pragma("unroll")                                                   \
            for (int nj_ = 0; nj_ < 4; nj_++) {                                 \
                uint32_t b0_[2] = { FB[nj_][0], FB[nj_][2] };                   \
                uint32_t b1_[2] = { FB[nj_][1], FB[nj_][3] };                   \
                mma16816(acc[mi_][2 * nj_],     FA[mi_], b0_);                  \
                mma16816(acc[mi_][2 * nj_ + 1], FA[mi_], b1_);                  \
            } } while (0)

    ISSUE(0, 0);
    asm volatile("cp.async.commit_group;\n");
    ISSUE(1, 1);
    asm volatile("cp.async.commit_group;\n");

    uint32_t fa[2][4][4], fb[2][4][4];

    #pragma unroll
    for (int it = 0; it < 4; it++) {
        if (it < 3) asm volatile("cp.async.wait_group 1;\n" ::: "memory");
        else        asm volatile("cp.async.wait_group 0;\n" ::: "memory");
        __syncthreads();
        if (it < 2) {
            ISSUE(it + 2, (it + 2) % 3);
            asm volatile("cp.async.commit_group;\n");
        }

        int buf = it % 3;
        uint32_t Ab = sb + SM_A + buf * 16384;
        uint32_t Bb = sb + SM_B + buf * 16384;

        // Register-double-buffered fragment pipeline over 4 k-chunks.
        LOADFRAG(fa[0], fb[0], Ab, Bb, (0 * 2 + l16));
        #pragma unroll
        for (int ks = 0; ks < 4; ks++) {
            int cur = ks & 1;
            if (ks < 3)
                LOADFRAG(fa[cur ^ 1], fb[cur ^ 1], Ab, Bb, ((ks + 1) * 2 + l16));
            DOMMA(fa[cur], fb[cur]);
        }
    }
#undef ISSUE
#undef LOADFRAG
#undef DOMMA
    __syncthreads();

    // Epilogue: MUFU exp + row sums + own-block sums + wm-selected cos
    // scatter. 128-aligned m-window lies in one 512-wide class block.
    int cls = m0 >> 9;
    int mbase = (m0 & 511) + wnw * 64;   // 64-aligned offset in class block
    int msel = mbase >> 8;               // which half this warp's cols fall in
    int moff = mbase & 255;              // offset within that half

    #pragma unroll
    for (int mi = 0; mi < 4; mi++) {
        int p0 = wmw * 64 + mi * 16 + g;
        int p1 = p0 + 8;
        bool own0 = (s_lab[p0] == cls);
        bool own1 = (s_lab[p1] == cls);
        bool sel0 = own0 && (s_hb[p0] == msel);
        bool sel1 = own1 && (s_hb[p1] == msel);
        float s0 = 0.0f, s1 = 0.0f;
        #pragma unroll
        for (int ni = 0; ni < 8; ni++) {
            float d0 = acc[mi][ni][0], d1 = acc[mi][ni][1];
            float d2 = acc[mi][ni][2], d3 = acc[mi][ni][3];
            s0 += fexp2c(d0) + fexp2c(d1);
            s1 += fexp2c(d2) + fexp2c(d3);
            int mo = moff + ni * 8 + t4 * 2;
            if (sel0) {
                float2 v; v.x = d0; v.y = d1;
                *(float2*)&g_owncos[(size_t)(n0 + p0) * SS + mo] = v;
            }
            if (sel1) {
                float2 v; v.x = d2; v.y = d3;
                *(float2*)&g_owncos[(size_t)(n0 + p1) * SS + mo] = v;
            }
        }
        s0 += __shfl_xor_sync(0xffffffffu, s0, 1);
        s0 += __shfl_xor_sync(0xffffffffu, s0, 2);
        s1 += __shfl_xor_sync(0xffffffffu, s1, 1);
        s1 += __shfl_xor_sync(0xffffffffu, s1, 2);
        if (t4 == 0) {
            atomicAdd(&s_rowsum[p0], s0);
            atomicAdd(&s_rowsum[p1], s1);
            if (own0) atomicAdd(&s_blksum[p0], s0);
            if (own1) atomicAdd(&s_blksum[p1], s1);
        }
    }
    __syncthreads();
    atomicAdd(&g_total[n0 + tid], s_rowsum[tid]);
    {
        float bsv = s_blksum[tid];
        if (bsv != 0.0f) atomicAdd(&g_blocksum[n0 + tid], bsv);
    }
}

// ---------------------------------------------------------------------------
// K3: one warp per pixel. down = total - blocksum; the stored values are
// already the wm-selected half: sum -log(pos/(pos+down+eps)+eps).
// Masked pixels accumulate straight into the 19-entry per-class globals.
// ---------------------------------------------------------------------------
__global__ void k_terms(const unsigned char* __restrict__ mask,
                        const int* __restrict__ labels) {
    int gw   = (blockIdx.x * blockDim.x + threadIdx.x) >> 5;
    int lane = threadIdx.x & 31;
    if (gw >= NN) return;
    int n = gw;

    if (!mask[n]) return;   // unmasked pixels contribute nothing

    float down = g_total[n] - g_blocksum[n];

    float ts = 0.0f;
    #pragma unroll
    for (int k = 0; k < 8; k++) {
        float c = g_owncos[(size_t)n * SS + lane + 32 * k];
        float pos = fexp2c(c);
        float r = pos / (pos + down + 1e-12f);
        ts += -logf(r + 1e-12f);
    }
    #pragma unroll
    for (int o = 16; o > 0; o >>= 1) ts += __shfl_xor_sync(0xffffffffu, ts, o);

    if (lane == 0) {
        int c = labels[n];
        atomicAdd(&g_contrib[c], ts);
        atomicAdd(&g_cnt[c], 1);
    }
}

// ---------------------------------------------------------------------------
// K4: reduce 19 per-class entries -> final scalar. One warp.
// ---------------------------------------------------------------------------
__global__ void k_final(float* __restrict__ out) {
    int t = threadIdx.x;
    float loss = 0.0f, ccount = 0.0f;
    if (t < CC) {
        int c = g_cnt[t];
        if (c > 0) {
            loss = g_contrib[t] / ((float)c * (float)SS);
            ccount = 1.0f;
        }
    }
    #pragma unroll
    for (int o = 16; o > 0; o >>= 1) {
        loss   += __shfl_xor_sync(0xffffffffu, loss, o);
        ccount += __shfl_xor_sync(0xffffffffu, ccount, o);
    }
    if (t == 0) out[0] = loss / fmaxf(ccount, 1.0f);
}

// ---------------------------------------------------------------------------
extern "C" void kernel_launch(void* const* d_in, const int* in_sizes, int n_in,
                              void* d_out, int out_size) {
    const float*         mem    = (const float*)d_in[0];         // (19,512,256)
    const float*         pred   = (const float*)d_in[1];         // (4,256,64,64)
    const int*           labels = (const int*)d_in[2];           // (4,64,64)
    const unsigned char* mask   = (const unsigned char*)d_in[3]; // bool (1B)
    const int*           wm     = (const int*)d_in[4];           // (4,64,64)
    float*               out    = (float*)d_out;

    (void)in_sizes; (void)n_in; (void)out_size;

    cudaFuncSetAttribute(k_gemm, cudaFuncAttributeMaxDynamicSharedMemorySize, SM_TOTAL);

    k_prep<<<64 + MM / 2, 256>>>(pred, mem);
    k_gemm<<<dim3(MM / 128, NN / 128), 128, SM_TOTAL>>>(labels, wm);
    k_terms<<<NN / 8, 256>>>(mask, labels);
    k_final<<<1, 32>>>(out);
}